// round 7
// baseline (speedup 1.0000x reference)
#include <cuda_runtime.h>

// RoutingLayer: capsule dynamic routing.
//   N=50000 nodes, M=32 neighbors, D=128 = K(8) x DELTA_D(16), max_iter=6 (fixed by setup_inputs).
// Inputs (metadata order): x fp32 [N,128], neighbors int32 [N*32] (JAX x64 disabled), max_iter.
// Output: u fp32 [N,128].

#define N_NODES 50000
#define M_NB    32
#define D_DIM   128
#define K_CAPS  8
#define DD      16
#define MAX_IT  6
#define EPS_N   1e-12f

// Scratch: per-capsule L2-normalized x. Index >= N (padding) handled by bounds check.
__device__ float g_xn[(size_t)N_NODES * D_DIM];

// ---------------------------------------------------------------------------
// Kernel 1: per-capsule normalize x into g_xn.
// 4 lanes per capsule (each lane a float4 of the 16-wide capsule).
// ---------------------------------------------------------------------------
__global__ void __launch_bounds__(256) caps_normalize_kernel(const float* __restrict__ x)
{
    int c = blockIdx.x * 64 + (threadIdx.x >> 2);   // capsule index (N*K total)
    int j = threadIdx.x & 3;                        // float4 slot within capsule
    if (c >= N_NODES * K_CAPS) return;

    const float4 v = __ldg(reinterpret_cast<const float4*>(x + (size_t)c * DD + 4 * j));
    float ss = v.x * v.x + v.y * v.y + v.z * v.z + v.w * v.w;
    ss += __shfl_xor_sync(0xffffffffu, ss, 1);
    ss += __shfl_xor_sync(0xffffffffu, ss, 2);
    float nrm = sqrtf(ss);
    float inv = 1.0f / fmaxf(nrm, EPS_N);
    float4 o = make_float4(v.x * inv, v.y * inv, v.z * inv, v.w * inv);
    *reinterpret_cast<float4*>(g_xn + (size_t)c * DD + 4 * j) = o;
}

// ---------------------------------------------------------------------------
// Kernel 2: routing iterations. One CTA (256 thr) per node.
//   warp w (0..7) owns m in {4w .. 4w+3}; lane l owns d in {4l .. 4l+3}.
//   z tile (32x128) lives entirely in registers (float4 z[4] per thread).
// Per iter:
//   p-phase : dot(z[m,k,:], u[k,:]) via 2 intra-capsule shuffles; softmax over
//             k via 3 butterfly shuffles (no max-sub: |dot| <= 1, unit vectors).
//   u-phase : warp-local weighted sum -> smem partial; 128 threads reduce
//             8 partials + x_c, renormalize per capsule (4 shuffles + rsqrtf).
// ---------------------------------------------------------------------------
__global__ void __launch_bounds__(256) routing_kernel(const int* __restrict__ neighbors,
                                                      float* __restrict__ out)
{
    const int n    = blockIdx.x;
    const int tid  = threadIdx.x;
    const int w    = tid >> 5;
    const int lane = tid & 31;

    __shared__ int   nbrow[M_NB];
    __shared__ float u_s[D_DIM];
    __shared__ float xc_s[D_DIM];
    __shared__ float part[8 * 132];   // 132-float stride: conflict-free patterns

    if (tid < M_NB) {
        nbrow[tid] = neighbors[(size_t)n * M_NB + tid];
    }
    if (tid < D_DIM) {
        xc_s[tid] = g_xn[(size_t)n * D_DIM + tid];
    }
    __syncthreads();

    // Gather z rows into registers (coalesced: warp reads 512B contiguous per row).
    float4 z[4];
#pragma unroll
    for (int q = 0; q < 4; q++) {
        int r = nbrow[w * 4 + q];
        if ((unsigned)r < (unsigned)N_NODES) {
            z[q] = __ldg(reinterpret_cast<const float4*>(g_xn + (size_t)r * D_DIM + 4 * lane));
        } else {
            z[q] = make_float4(0.f, 0.f, 0.f, 0.f);   // padding row (index == N)
        }
    }

#pragma unroll
    for (int it = 0; it < MAX_IT; it++) {
        float p[4];
        if (it == 0) {
            // softmax(zeros) over K=8
            p[0] = p[1] = p[2] = p[3] = 0.125f;
        } else {
            const float4 u4 = *reinterpret_cast<const float4*>(u_s + 4 * lane);
#pragma unroll
            for (int q = 0; q < 4; q++) {
                float s = z[q].x * u4.x + z[q].y * u4.y + z[q].z * u4.z + z[q].w * u4.w;
                // full 16-wide capsule dot across the 4-lane group
                s += __shfl_xor_sync(0xffffffffu, s, 1);
                s += __shfl_xor_sync(0xffffffffu, s, 2);
                // softmax over k (8 capsule groups of 4 lanes each). |s| <= 1 ->
                // no max-subtraction needed (identical in exact arithmetic).
                float e = __expf(s);
                float t = e;
                t += __shfl_xor_sync(0xffffffffu, t, 4);
                t += __shfl_xor_sync(0xffffffffu, t, 8);
                t += __shfl_xor_sync(0xffffffffu, t, 16);
                p[q] = __fdividef(e, t);
            }
        }

        // warp-local weighted accumulation over its 4 m's
        float4 acc = make_float4(0.f, 0.f, 0.f, 0.f);
#pragma unroll
        for (int q = 0; q < 4; q++) {
            acc.x = fmaf(z[q].x, p[q], acc.x);
            acc.y = fmaf(z[q].y, p[q], acc.y);
            acc.z = fmaf(z[q].z, p[q], acc.z);
            acc.w = fmaf(z[q].w, p[q], acc.w);
        }
        *reinterpret_cast<float4*>(part + w * 132 + 4 * lane) = acc;
        __syncthreads();

        if (tid < D_DIM) {
            float v = xc_s[tid];
#pragma unroll
            for (int w2 = 0; w2 < 8; w2++) v += part[w2 * 132 + tid];

            if (it < MAX_IT - 1) {
                // per-capsule renormalize (16 contiguous lanes per capsule)
                float ss = v * v;
                ss += __shfl_xor_sync(0xffffffffu, ss, 1);
                ss += __shfl_xor_sync(0xffffffffu, ss, 2);
                ss += __shfl_xor_sync(0xffffffffu, ss, 4);
                ss += __shfl_xor_sync(0xffffffffu, ss, 8);
                float inv = rsqrtf(fmaxf(ss, EPS_N * EPS_N));
                u_s[tid] = v * inv;
            } else {
                // last iteration: no normalize, write result
                out[(size_t)n * D_DIM + tid] = v;
            }
        }
        __syncthreads();
    }
}

// ---------------------------------------------------------------------------
extern "C" void kernel_launch(void* const* d_in, const int* in_sizes, int n_in,
                              void* d_out, int out_size)
{
    const float* x   = (const float*)d_in[0];
    const int*   nb  = (const int*)d_in[1];     // int32: JAX x64 is disabled by default
    float*       out = (float*)d_out;
    (void)in_sizes; (void)n_in; (void)out_size;  // shapes fixed; max_iter fixed = 6

    // 1) per-capsule normalize x -> g_xn
    {
        int caps   = N_NODES * K_CAPS;           // 400000
        int blocks = (caps + 63) / 64;           // 64 capsules per 256-thread block
        caps_normalize_kernel<<<blocks, 256>>>(x);
    }
    // 2) routing
    routing_kernel<<<N_NODES, 256>>>(nb, out);
}

// round 8
// speedup vs baseline: 1.0347x; 1.0347x over previous
#include <cuda_runtime.h>

// RoutingLayer: capsule dynamic routing.
//   N=50000 nodes, M=32 neighbors, D=128 = K(8) x DELTA_D(16), max_iter=6.
// Inputs: x fp32 [N,128], neighbors int32 [N*32], max_iter (fixed 6).
// Output: u fp32 [N,128].

#define N_NODES 50000
#define M_NB    32
#define D_DIM   128
#define K_CAPS  8
#define MAX_IT  6
#define EPS_N   1e-12f

// Scratch: per-capsule L2-normalized x.
__device__ float g_xn[(size_t)N_NODES * D_DIM];

// ---------------------------------------------------------------------------
// Kernel 1: per-capsule normalize x into g_xn (4 lanes per 16-wide capsule).
// ---------------------------------------------------------------------------
__global__ void __launch_bounds__(256) caps_normalize_kernel(const float* __restrict__ x)
{
    int c = blockIdx.x * 64 + (threadIdx.x >> 2);
    int j = threadIdx.x & 3;
    if (c >= N_NODES * K_CAPS) return;

    const float4 v = __ldg(reinterpret_cast<const float4*>(x + (size_t)c * 16 + 4 * j));
    float ss = v.x * v.x + v.y * v.y + v.z * v.z + v.w * v.w;
    ss += __shfl_xor_sync(0xffffffffu, ss, 1);
    ss += __shfl_xor_sync(0xffffffffu, ss, 2);
    float inv = 1.0f / fmaxf(sqrtf(ss), EPS_N);
    float4 o = make_float4(v.x * inv, v.y * inv, v.z * inv, v.w * inv);
    *reinterpret_cast<float4*>(g_xn + (size_t)c * 16 + 4 * j) = o;
}

// ---------------------------------------------------------------------------
// Kernel 2: routing. One 128-thread CTA per node.
//   warp w (0..3) owns m in {8w .. 8w+7}; lane l owns d in {4l .. 4l+3}.
//   z tile (32x128) in registers: 8 x float4 per thread.
//   Per iter: p-phase fused with weighted accumulation (5 shuffles + EX2 +
//   RCP per m); one smem round-trip (4 x 512B partials, float4 both ways);
//   all 4 warps redundantly reduce -> u stays in registers; no u_s, no xc_s.
// ---------------------------------------------------------------------------
__global__ void __launch_bounds__(128) routing_kernel(const int* __restrict__ neighbors,
                                                      float* __restrict__ out)
{
    const int n    = blockIdx.x;
    const int tid  = threadIdx.x;
    const int w    = tid >> 5;
    const int lane = tid & 31;

    __shared__ float part[4 * 132];   // padded rows; float4-friendly

    // Warp w's 8 neighbor indices: lanes 0..7 load, distribute via shuffle.
    int r_my = 0;
    if (lane < 8) r_my = neighbors[(size_t)n * M_NB + w * 8 + lane];

    // Gather z rows into registers (each row: one warp reads 512B contiguous).
    float4 z[8];
#pragma unroll
    for (int q = 0; q < 8; q++) {
        int r = __shfl_sync(0xffffffffu, r_my, q);
        if ((unsigned)r < (unsigned)N_NODES) {
            z[q] = __ldg(reinterpret_cast<const float4*>(g_xn + (size_t)r * D_DIM + 4 * lane));
        } else {
            z[q] = make_float4(0.f, 0.f, 0.f, 0.f);   // padding row (index == N)
        }
    }

    // x_c slice for this thread's d's (register-resident for all iterations).
    const float4 xc = __ldg(reinterpret_cast<const float4*>(g_xn + (size_t)n * D_DIM + 4 * lane));

    float4 u4 = make_float4(0.f, 0.f, 0.f, 0.f);      // valid from iter 1 on

#pragma unroll
    for (int it = 0; it < MAX_IT; it++) {
        float4 acc = make_float4(0.f, 0.f, 0.f, 0.f);

        if (it == 0) {
            // softmax(zeros): p = 1/8 uniformly
#pragma unroll
            for (int q = 0; q < 8; q++) {
                acc.x += z[q].x; acc.y += z[q].y; acc.z += z[q].z; acc.w += z[q].w;
            }
            acc.x *= 0.125f; acc.y *= 0.125f; acc.z *= 0.125f; acc.w *= 0.125f;
        } else {
#pragma unroll
            for (int q = 0; q < 8; q++) {
                // capsule dot: 4 lanes x float4 -> 16-wide dot
                float s = z[q].x * u4.x + z[q].y * u4.y + z[q].z * u4.z + z[q].w * u4.w;
                s += __shfl_xor_sync(0xffffffffu, s, 1);
                s += __shfl_xor_sync(0xffffffffu, s, 2);
                // softmax over k (8 capsule groups). |s| <= 1 (unit x unit) ->
                // no max-subtraction needed.
                float e = __expf(s);
                float t = e;
                t += __shfl_xor_sync(0xffffffffu, t, 4);
                t += __shfl_xor_sync(0xffffffffu, t, 8);
                t += __shfl_xor_sync(0xffffffffu, t, 16);
                float p = __fdividef(e, t);
                acc.x = fmaf(z[q].x, p, acc.x);
                acc.y = fmaf(z[q].y, p, acc.y);
                acc.z = fmaf(z[q].z, p, acc.z);
                acc.w = fmaf(z[q].w, p, acc.w);
            }
        }

        // one smem round-trip: 4 x 512B partials
        *reinterpret_cast<float4*>(part + w * 132 + 4 * lane) = acc;
        __syncthreads();

        float4 v = xc;
#pragma unroll
        for (int w2 = 0; w2 < 4; w2++) {
            float4 pv = *reinterpret_cast<const float4*>(part + w2 * 132 + 4 * lane);
            v.x += pv.x; v.y += pv.y; v.z += pv.z; v.w += pv.w;
        }

        if (it < MAX_IT - 1) {
            // per-capsule renormalize (capsule = 4 lanes x float4)
            float ss = v.x * v.x + v.y * v.y + v.z * v.z + v.w * v.w;
            ss += __shfl_xor_sync(0xffffffffu, ss, 1);
            ss += __shfl_xor_sync(0xffffffffu, ss, 2);
            float inv = rsqrtf(fmaxf(ss, EPS_N * EPS_N));
            u4.x = v.x * inv; u4.y = v.y * inv; u4.z = v.z * inv; u4.w = v.w * inv;
            __syncthreads();   // protect part[] before next iter's store
        } else {
            if (w == 0) {      // all warps hold identical v; warp 0 writes 512B
                *reinterpret_cast<float4*>(out + (size_t)n * D_DIM + 4 * lane) = v;
            }
        }
    }
}

// ---------------------------------------------------------------------------
extern "C" void kernel_launch(void* const* d_in, const int* in_sizes, int n_in,
                              void* d_out, int out_size)
{
    const float* x   = (const float*)d_in[0];
    const int*   nb  = (const int*)d_in[1];
    float*       out = (float*)d_out;
    (void)in_sizes; (void)n_in; (void)out_size;

    int caps   = N_NODES * K_CAPS;
    int blocks = (caps + 63) / 64;
    caps_normalize_kernel<<<blocks, 256>>>(x);

    routing_kernel<<<N_NODES, 128>>>(nb, out);
}

// round 9
// speedup vs baseline: 1.4483x; 1.3997x over previous
#include <cuda_runtime.h>

// RoutingLayer: capsule dynamic routing.
//   N=50000, M=32 neighbors, D=128 = K(8) x 16, max_iter=6.
// Inputs: x fp32 [N,128], neighbors int32 [N*32], max_iter (fixed 6).
// Output: u fp32 [N,128].

#define N_NODES 50000
#define M_NB    32
#define D_DIM   128
#define K_CAPS  8
#define MAX_IT  6
#define EPS_N   1e-12f
#define FULLM   0xffffffffu

// Scratch: per-capsule L2-normalized x.
__device__ float g_xn[(size_t)N_NODES * D_DIM];

// ---------------------------------------------------------------------------
// Kernel 1: per-capsule normalize x into g_xn (4 lanes per 16-wide capsule).
// ---------------------------------------------------------------------------
__global__ void __launch_bounds__(256) caps_normalize_kernel(const float* __restrict__ x)
{
    int c = blockIdx.x * 64 + (threadIdx.x >> 2);
    int j = threadIdx.x & 3;
    if (c >= N_NODES * K_CAPS) return;

    const float4 v = __ldg(reinterpret_cast<const float4*>(x + (size_t)c * 16 + 4 * j));
    float ss = v.x * v.x + v.y * v.y + v.z * v.z + v.w * v.w;
    ss += __shfl_xor_sync(FULLM, ss, 1);
    ss += __shfl_xor_sync(FULLM, ss, 2);
    float inv = 1.0f / fmaxf(sqrtf(ss), EPS_N);
    float4 o = make_float4(v.x * inv, v.y * inv, v.z * inv, v.w * inv);
    *reinterpret_cast<float4*>(g_xn + (size_t)c * 16 + 4 * j) = o;
}

// ---------------------------------------------------------------------------
// Kernel 2: routing. One 128-thread CTA per node.
//   warp w owns m in {8w..8w+7}; lane l owns d-slice float4 (capsule k=l>>2).
//   p-phase: reduce-scatter (6 shfl) -> softmax on 2 vals/lane (2 exp,
//   6 shfl, 2 div) -> allgather (6 shfl). 20 shfl total vs 42 naive.
//   One double-buffered smem round trip per iter; u, x_c in registers.
// ---------------------------------------------------------------------------
__global__ void __launch_bounds__(128) routing_kernel(const int* __restrict__ neighbors,
                                                      float* __restrict__ out)
{
    const int n    = blockIdx.x;
    const int tid  = threadIdx.x;
    const int w    = tid >> 5;
    const int lane = tid & 31;
    const bool b0  = (lane & 1) != 0;
    const bool b1  = (lane & 2) != 0;

    __shared__ float part[2][4 * 132];   // double-buffered partials

    // Warp w's 8 neighbor indices: lanes 0..7 load, distribute via shuffle.
    int r_my = 0;
    if (lane < 8) r_my = neighbors[(size_t)n * M_NB + w * 8 + lane];

    // Gather z rows into registers (each row: one warp reads 512B contiguous).
    float4 z[8];
#pragma unroll
    for (int q = 0; q < 8; q++) {
        int r = __shfl_sync(FULLM, r_my, q);
        if ((unsigned)r < (unsigned)N_NODES) {
            z[q] = __ldg(reinterpret_cast<const float4*>(g_xn + (size_t)r * D_DIM + 4 * lane));
        } else {
            z[q] = make_float4(0.f, 0.f, 0.f, 0.f);   // padding row (index == N)
        }
    }

    const float4 xc = __ldg(reinterpret_cast<const float4*>(g_xn + (size_t)n * D_DIM + 4 * lane));

    float4 u4;

    // ---- iteration 0: p = 1/8 uniformly ----
    {
        float4 acc = make_float4(0.f, 0.f, 0.f, 0.f);
#pragma unroll
        for (int q = 0; q < 8; q++) {
            acc.x += z[q].x; acc.y += z[q].y; acc.z += z[q].z; acc.w += z[q].w;
        }
        acc.x *= 0.125f; acc.y *= 0.125f; acc.z *= 0.125f; acc.w *= 0.125f;

        *reinterpret_cast<float4*>(&part[0][w * 132 + 4 * lane]) = acc;
        __syncthreads();
        float4 v = xc;
#pragma unroll
        for (int w2 = 0; w2 < 4; w2++) {
            float4 pv = *reinterpret_cast<const float4*>(&part[0][w2 * 132 + 4 * lane]);
            v.x += pv.x; v.y += pv.y; v.z += pv.z; v.w += pv.w;
        }
        float ss = v.x * v.x + v.y * v.y + v.z * v.z + v.w * v.w;
        ss += __shfl_xor_sync(FULLM, ss, 1);
        ss += __shfl_xor_sync(FULLM, ss, 2);
        float inv = rsqrtf(fmaxf(ss, EPS_N * EPS_N));
        u4 = make_float4(v.x * inv, v.y * inv, v.z * inv, v.w * inv);
    }

    // ---- iterations 1..5 ----
#pragma unroll
    for (int it = 1; it < MAX_IT; it++) {
        // lane-partial dots (4 of the 16 capsule dims per lane)
        float sp[8];
#pragma unroll
        for (int q = 0; q < 8; q++) {
            sp[q] = z[q].x * u4.x + z[q].y * u4.y + z[q].z * u4.z + z[q].w * u4.w;
        }

        // reduce-scatter over xor1: a[j] = 2-lane sum of q = 2j + b0
        float a0, a1, a2, a3;
        {
            float sd, kp;
            sd = b0 ? sp[0] : sp[1]; kp = b0 ? sp[1] : sp[0];
            a0 = kp + __shfl_xor_sync(FULLM, sd, 1);
            sd = b0 ? sp[2] : sp[3]; kp = b0 ? sp[3] : sp[2];
            a1 = kp + __shfl_xor_sync(FULLM, sd, 1);
            sd = b0 ? sp[4] : sp[5]; kp = b0 ? sp[5] : sp[4];
            a2 = kp + __shfl_xor_sync(FULLM, sd, 1);
            sd = b0 ? sp[6] : sp[7]; kp = b0 ? sp[7] : sp[6];
            a3 = kp + __shfl_xor_sync(FULLM, sd, 1);
        }
        // reduce-scatter over xor2: s_i = full 16-dot for q = 4i + (lane&3)
        float s0, s1;
        {
            float sd, kp;
            sd = b1 ? a0 : a1; kp = b1 ? a1 : a0;
            s0 = kp + __shfl_xor_sync(FULLM, sd, 2);
            sd = b1 ? a2 : a3; kp = b1 ? a3 : a2;
            s1 = kp + __shfl_xor_sync(FULLM, sd, 2);
        }

        // softmax over k (stride-4 lanes share (lane&3), k varies).
        // |s| <= 1 (unit x unit capsules) -> no max-subtraction needed.
        float e0 = __expf(s0), e1 = __expf(s1);
        float t0 = e0, t1 = e1;
        t0 += __shfl_xor_sync(FULLM, t0, 4);
        t1 += __shfl_xor_sync(FULLM, t1, 4);
        t0 += __shfl_xor_sync(FULLM, t0, 8);
        t1 += __shfl_xor_sync(FULLM, t1, 8);
        t0 += __shfl_xor_sync(FULLM, t0, 16);
        t1 += __shfl_xor_sync(FULLM, t1, 16);
        float p0 = __fdividef(e0, t0);   // p[q = lane&3,     k = lane>>2]
        float p1 = __fdividef(e1, t1);   // p[q = 4 + lane&3, k = lane>>2]

        // allgather over xor2
        float o0 = __shfl_xor_sync(FULLM, p0, 2);
        float o1 = __shfl_xor_sync(FULLM, p1, 2);
        float c00 = b1 ? o0 : p0;   // q = 0 + b0
        float c01 = b1 ? p0 : o0;   // q = 2 + b0
        float c10 = b1 ? o1 : p1;   // q = 4 + b0
        float c11 = b1 ? p1 : o1;   // q = 6 + b0
        // allgather over xor1 -> p replicated for all 8 q
        float pf[8], r;
        r = __shfl_xor_sync(FULLM, c00, 1);
        pf[0] = b0 ? r : c00;  pf[1] = b0 ? c00 : r;
        r = __shfl_xor_sync(FULLM, c01, 1);
        pf[2] = b0 ? r : c01;  pf[3] = b0 ? c01 : r;
        r = __shfl_xor_sync(FULLM, c10, 1);
        pf[4] = b0 ? r : c10;  pf[5] = b0 ? c10 : r;
        r = __shfl_xor_sync(FULLM, c11, 1);
        pf[6] = b0 ? r : c11;  pf[7] = b0 ? c11 : r;

        // weighted accumulation over this warp's 8 m's
        float4 acc = make_float4(0.f, 0.f, 0.f, 0.f);
#pragma unroll
        for (int q = 0; q < 8; q++) {
            acc.x = fmaf(z[q].x, pf[q], acc.x);
            acc.y = fmaf(z[q].y, pf[q], acc.y);
            acc.z = fmaf(z[q].z, pf[q], acc.z);
            acc.w = fmaf(z[q].w, pf[q], acc.w);
        }

        // cross-warp reduce via double-buffered smem (single sync per iter)
        float* pb = part[it & 1];
        *reinterpret_cast<float4*>(&pb[w * 132 + 4 * lane]) = acc;
        __syncthreads();

        float4 v = xc;
#pragma unroll
        for (int w2 = 0; w2 < 4; w2++) {
            float4 pv = *reinterpret_cast<const float4*>(&pb[w2 * 132 + 4 * lane]);
            v.x += pv.x; v.y += pv.y; v.z += pv.z; v.w += pv.w;
        }

        if (it < MAX_IT - 1) {
            float ss = v.x * v.x + v.y * v.y + v.z * v.z + v.w * v.w;
            ss += __shfl_xor_sync(FULLM, ss, 1);
            ss += __shfl_xor_sync(FULLM, ss, 2);
            float inv = rsqrtf(fmaxf(ss, EPS_N * EPS_N));
            u4 = make_float4(v.x * inv, v.y * inv, v.z * inv, v.w * inv);
        } else {
            if (w == 0) {
                *reinterpret_cast<float4*>(out + (size_t)n * D_DIM + 4 * lane) = v;
            }
        }
    }
}

// ---------------------------------------------------------------------------
extern "C" void kernel_launch(void* const* d_in, const int* in_sizes, int n_in,
                              void* d_out, int out_size)
{
    const float* x   = (const float*)d_in[0];
    const int*   nb  = (const int*)d_in[1];
    float*       out = (float*)d_out;
    (void)in_sizes; (void)n_in; (void)out_size;

    int caps   = N_NODES * K_CAPS;
    int blocks = (caps + 63) / 64;
    caps_normalize_kernel<<<blocks, 256>>>(x);

    routing_kernel<<<N_NODES, 128>>>(nb, out);
}

// round 10
// speedup vs baseline: 1.6049x; 1.1082x over previous
#include <cuda_runtime.h>
#include <string.h>

// RoutingLayer: capsule dynamic routing.
//   N=50000, M=32 neighbors, D=128 = K(8) x 16, max_iter=6.
// Inputs: x fp32 [N,128], neighbors int32 [N*32], max_iter (fixed 6).
// Output: u fp32 [N,128].

#define N_NODES 50000
#define M_NB    32
#define D_DIM   128
#define K_CAPS  8
#define MAX_IT  6
#define EPS_N   1e-12f
#define FULLM   0xffffffffu

typedef unsigned long long u64;

// ---- f32x2 packed-math helpers (ptxas never auto-fuses FFMA2 from C++) ----
__device__ __forceinline__ u64 pack2(float a, float b) {
    u64 r; asm("mov.b64 %0,{%1,%2};" : "=l"(r) : "f"(a), "f"(b)); return r;
}
__device__ __forceinline__ float2 unpack2(u64 v) {
    float2 f; asm("mov.b64 {%0,%1},%2;" : "=f"(f.x), "=f"(f.y) : "l"(v)); return f;
}
__device__ __forceinline__ u64 fma2(u64 a, u64 b, u64 c) {
    u64 d; asm("fma.rn.f32x2 %0,%1,%2,%3;" : "=l"(d) : "l"(a), "l"(b), "l"(c)); return d;
}
__device__ __forceinline__ u64 mul2(u64 a, u64 b) {
    u64 d; asm("mul.rn.f32x2 %0,%1,%2;" : "=l"(d) : "l"(a), "l"(b)); return d;
}
__device__ __forceinline__ u64 add2(u64 a, u64 b) {
    u64 d; asm("add.rn.f32x2 %0,%1,%2;" : "=l"(d) : "l"(a), "l"(b)); return d;
}

// Scratch: per-capsule L2-normalized x.
__device__ float g_xn[(size_t)N_NODES * D_DIM];

// ---------------------------------------------------------------------------
// Kernel 1: per-capsule normalize x into g_xn (4 lanes per 16-wide capsule).
// ---------------------------------------------------------------------------
__global__ void __launch_bounds__(256) caps_normalize_kernel(const float* __restrict__ x)
{
    int c = blockIdx.x * 64 + (threadIdx.x >> 2);
    int j = threadIdx.x & 3;
    if (c >= N_NODES * K_CAPS) return;

    const float4 v = __ldg(reinterpret_cast<const float4*>(x + (size_t)c * 16 + 4 * j));
    float ss = v.x * v.x + v.y * v.y + v.z * v.z + v.w * v.w;
    ss += __shfl_xor_sync(FULLM, ss, 1);
    ss += __shfl_xor_sync(FULLM, ss, 2);
    float inv = 1.0f / fmaxf(sqrtf(ss), EPS_N);
    float4 o = make_float4(v.x * inv, v.y * inv, v.z * inv, v.w * inv);
    *reinterpret_cast<float4*>(g_xn + (size_t)c * 16 + 4 * j) = o;
}

// ---------------------------------------------------------------------------
// Kernel 2: routing. One 128-thread CTA per node.
//   p/acc-phase: warp w owns m {8w..8w+7}; lane owns d-slice [4l..4l+3]
//   (z in 16 x b64 register pairs, math in f32x2).
//   reduce-phase (split-d): warp w reduces d in [32w..32w+32), one d/lane,
//   scalar LDS; per-capsule renorm over 16 lanes; u broadcast via u_s.
// ---------------------------------------------------------------------------
__global__ void __launch_bounds__(128) routing_kernel(const int* __restrict__ neighbors,
                                                      float* __restrict__ out)
{
    const int n     = blockIdx.x;
    const int tid   = threadIdx.x;
    const int w     = tid >> 5;
    const int lane  = tid & 31;
    const bool b0   = (lane & 1) != 0;
    const bool b1   = (lane & 2) != 0;
    const int dmine = 32 * w + lane;         // this thread's d in reduce phase

    __shared__ float part[4 * 132];          // padded rows
    __shared__ float u_s[D_DIM];

    // Warp w's 8 neighbor indices: lanes 0..7 load, distribute via shuffle.
    int r_my = 0;
    if (lane < 8) r_my = neighbors[(size_t)n * M_NB + w * 8 + lane];

    // Gather z rows as b64 pairs (zl = d[4l..4l+1], zh = d[4l+2..4l+3]).
    u64 zl[8], zh[8];
#pragma unroll
    for (int q = 0; q < 8; q++) {
        int r = __shfl_sync(FULLM, r_my, q);
        if ((unsigned)r < (unsigned)N_NODES) {
            uint4 t = __ldg(reinterpret_cast<const uint4*>(g_xn + (size_t)r * D_DIM + 4 * lane));
            ulonglong2 zz; memcpy(&zz, &t, 16);
            zl[q] = zz.x; zh[q] = zz.y;
        } else {
            zl[q] = 0ull; zh[q] = 0ull;      // padding row (index == N)
        }
    }

    const float xcs = __ldg(g_xn + (size_t)n * D_DIM + dmine);

    u64 ul, uh;   // u for this lane's d-slice, packed

    // ---- iteration 0: p = 1/8 uniformly ----
    {
        u64 a0 = 0ull, a1 = 0ull;            // {0.f,0.f}
#pragma unroll
        for (int q = 0; q < 8; q++) { a0 = add2(a0, zl[q]); a1 = add2(a1, zh[q]); }
        const u64 eighth = pack2(0.125f, 0.125f);
        a0 = mul2(a0, eighth); a1 = mul2(a1, eighth);

        *reinterpret_cast<ulonglong2*>(&part[w * 132 + 4 * lane]) = make_ulonglong2(a0, a1);
        __syncthreads();

        float v = xcs;
#pragma unroll
        for (int w2 = 0; w2 < 4; w2++) v += part[w2 * 132 + dmine];

        float ss = v * v;                    // capsule = 16 consecutive lanes
        ss += __shfl_xor_sync(FULLM, ss, 1);
        ss += __shfl_xor_sync(FULLM, ss, 2);
        ss += __shfl_xor_sync(FULLM, ss, 4);
        ss += __shfl_xor_sync(FULLM, ss, 8);
        float inv = rsqrtf(fmaxf(ss, EPS_N * EPS_N));
        u_s[dmine] = v * inv;
        __syncthreads();

        uint4 t = *reinterpret_cast<const uint4*>(&u_s[4 * lane]);
        ulonglong2 uu; memcpy(&uu, &t, 16);
        ul = uu.x; uh = uu.y;
    }

    // ---- iterations 1..5 ----
#pragma unroll
    for (int it = 1; it < MAX_IT; it++) {
        // lane-partial dots (f32x2): sp[q] = z[q][4l..4l+3] . u[4l..4l+3]
        float sp[8];
#pragma unroll
        for (int q = 0; q < 8; q++) {
            float2 f = unpack2(fma2(zl[q], ul, mul2(zh[q], uh)));
            sp[q] = f.x + f.y;
        }

        // reduce-scatter over xor1: a[j] = 2-lane sum of q = 2j + b0
        float a0, a1, a2, a3;
        {
            float sd, kp;
            sd = b0 ? sp[0] : sp[1]; kp = b0 ? sp[1] : sp[0];
            a0 = kp + __shfl_xor_sync(FULLM, sd, 1);
            sd = b0 ? sp[2] : sp[3]; kp = b0 ? sp[3] : sp[2];
            a1 = kp + __shfl_xor_sync(FULLM, sd, 1);
            sd = b0 ? sp[4] : sp[5]; kp = b0 ? sp[5] : sp[4];
            a2 = kp + __shfl_xor_sync(FULLM, sd, 1);
            sd = b0 ? sp[6] : sp[7]; kp = b0 ? sp[7] : sp[6];
            a3 = kp + __shfl_xor_sync(FULLM, sd, 1);
        }
        // reduce-scatter over xor2: s_i = full 16-dot for q = 4i + (lane&3)
        float s0, s1;
        {
            float sd, kp;
            sd = b1 ? a0 : a1; kp = b1 ? a1 : a0;
            s0 = kp + __shfl_xor_sync(FULLM, sd, 2);
            sd = b1 ? a2 : a3; kp = b1 ? a3 : a2;
            s1 = kp + __shfl_xor_sync(FULLM, sd, 2);
        }

        // softmax over k. |s| <= 1 (unit x unit capsules) -> no max-sub.
        float e0 = __expf(s0), e1 = __expf(s1);
        float t0 = e0, t1 = e1;
        t0 += __shfl_xor_sync(FULLM, t0, 4);
        t1 += __shfl_xor_sync(FULLM, t1, 4);
        t0 += __shfl_xor_sync(FULLM, t0, 8);
        t1 += __shfl_xor_sync(FULLM, t1, 8);
        t0 += __shfl_xor_sync(FULLM, t0, 16);
        t1 += __shfl_xor_sync(FULLM, t1, 16);
        float p0 = __fdividef(e0, t0);
        float p1 = __fdividef(e1, t1);

        // allgather p back to all-q-replicated
        float o0 = __shfl_xor_sync(FULLM, p0, 2);
        float o1 = __shfl_xor_sync(FULLM, p1, 2);
        float c00 = b1 ? o0 : p0, c01 = b1 ? p0 : o0;
        float c10 = b1 ? o1 : p1, c11 = b1 ? p1 : o1;
        float pf[8], r;
        r = __shfl_xor_sync(FULLM, c00, 1); pf[0] = b0 ? r : c00; pf[1] = b0 ? c00 : r;
        r = __shfl_xor_sync(FULLM, c01, 1); pf[2] = b0 ? r : c01; pf[3] = b0 ? c01 : r;
        r = __shfl_xor_sync(FULLM, c10, 1); pf[4] = b0 ? r : c10; pf[5] = b0 ? c10 : r;
        r = __shfl_xor_sync(FULLM, c11, 1); pf[6] = b0 ? r : c11; pf[7] = b0 ? c11 : r;

        // weighted accumulation (f32x2)
        u64 acc0 = 0ull, acc1 = 0ull;
#pragma unroll
        for (int q = 0; q < 8; q++) {
            u64 pp = pack2(pf[q], pf[q]);
            acc0 = fma2(zl[q], pp, acc0);
            acc1 = fma2(zh[q], pp, acc1);
        }

        *reinterpret_cast<ulonglong2*>(&part[w * 132 + 4 * lane]) = make_ulonglong2(acc0, acc1);
        __syncthreads();

        // split-d reduce: this thread owns d = dmine
        float v = xcs;
#pragma unroll
        for (int w2 = 0; w2 < 4; w2++) v += part[w2 * 132 + dmine];

        if (it < MAX_IT - 1) {
            float ss = v * v;
            ss += __shfl_xor_sync(FULLM, ss, 1);
            ss += __shfl_xor_sync(FULLM, ss, 2);
            ss += __shfl_xor_sync(FULLM, ss, 4);
            ss += __shfl_xor_sync(FULLM, ss, 8);
            float inv = rsqrtf(fmaxf(ss, EPS_N * EPS_N));
            u_s[dmine] = v * inv;
            __syncthreads();
            uint4 t = *reinterpret_cast<const uint4*>(&u_s[4 * lane]);
            ulonglong2 uu; memcpy(&uu, &t, 16);
            ul = uu.x; uh = uu.y;
        } else {
            // last iteration: no renormalize; 128 threads write 512B coalesced
            out[(size_t)n * D_DIM + dmine] = v;
        }
    }
}

// ---------------------------------------------------------------------------
extern "C" void kernel_launch(void* const* d_in, const int* in_sizes, int n_in,
                              void* d_out, int out_size)
{
    const float* x   = (const float*)d_in[0];
    const int*   nb  = (const int*)d_in[1];
    float*       out = (float*)d_out;
    (void)in_sizes; (void)n_in; (void)out_size;

    int caps   = N_NODES * K_CAPS;
    int blocks = (caps + 63) / 64;
    caps_normalize_kernel<<<blocks, 256>>>(x);

    routing_kernel<<<N_NODES, 128>>>(nb, out);
}

// round 12
// speedup vs baseline: 1.6355x; 1.0191x over previous
#include <cuda_runtime.h>
#include <string.h>

// RoutingLayer: capsule dynamic routing.
//   N=50000, M=32 neighbors, D=128 = K(8) x 16, max_iter=6.
// Inputs: x fp32 [N,128], neighbors int32 [N*32], max_iter (fixed 6).
// Output: u fp32 [N,128].

#define N_NODES 50000
#define M_NB    32
#define D_DIM   128
#define K_CAPS  8
#define MAX_IT  6
#define EPS_N   1e-12f
#define FULLM   0xffffffffu

typedef unsigned long long u64;

// ---- f32x2 packed-math helpers (ptxas never auto-fuses FFMA2 from C++) ----
__device__ __forceinline__ u64 pack2(float a, float b) {
    u64 r; asm("mov.b64 %0,{%1,%2};" : "=l"(r) : "f"(a), "f"(b)); return r;
}
__device__ __forceinline__ float2 unpack2(u64 v) {
    float2 f; asm("mov.b64 {%0,%1},%2;" : "=f"(f.x), "=f"(f.y) : "l"(v)); return f;
}
__device__ __forceinline__ u64 fma2(u64 a, u64 b, u64 c) {
    u64 d; asm("fma.rn.f32x2 %0,%1,%2,%3;" : "=l"(d) : "l"(a), "l"(b), "l"(c)); return d;
}
__device__ __forceinline__ u64 mul2(u64 a, u64 b) {
    u64 d; asm("mul.rn.f32x2 %0,%1,%2;" : "=l"(d) : "l"(a), "l"(b)); return d;
}
__device__ __forceinline__ u64 add2(u64 a, u64 b) {
    u64 d; asm("add.rn.f32x2 %0,%1,%2;" : "=l"(d) : "l"(a), "l"(b)); return d;
}

// Scratch: per-capsule L2-normalized x.
__device__ float g_xn[(size_t)N_NODES * D_DIM];

// ---------------------------------------------------------------------------
// Kernel 1: per-capsule normalize x into g_xn (4 lanes per 16-wide capsule).
// ---------------------------------------------------------------------------
__global__ void __launch_bounds__(256) caps_normalize_kernel(const float* __restrict__ x)
{
    int c = blockIdx.x * 64 + (threadIdx.x >> 2);
    int j = threadIdx.x & 3;
    if (c >= N_NODES * K_CAPS) return;

    const float4 v = __ldg(reinterpret_cast<const float4*>(x + (size_t)c * 16 + 4 * j));
    float ss = v.x * v.x + v.y * v.y + v.z * v.z + v.w * v.w;
    ss += __shfl_xor_sync(FULLM, ss, 1);
    ss += __shfl_xor_sync(FULLM, ss, 2);
    float inv = 1.0f / fmaxf(sqrtf(ss), EPS_N);
    float4 o = make_float4(v.x * inv, v.y * inv, v.z * inv, v.w * inv);
    *reinterpret_cast<float4*>(g_xn + (size_t)c * 16 + 4 * j) = o;
}

// ---------------------------------------------------------------------------
// Kernel 2: routing. One 128-thread CTA per node.
//   p/acc-phase: warp w owns m {8w..8w+7}; lane owns d-slice [4l..4l+3]
//   (z as b64 pairs, math in f32x2). Dots via 6-shfl reduce-scatter;
//   softmax k-sums via 3-shfl butterflies (f32 REDUX not on sm_103);
//   p allgather via 384B/warp smem exchange (2 STS + 2 LDS.128,
//   conflict-free: {12*kk + c} mod 32 all distinct).
//   reduce-phase (split-d): warp w reduces d in [32w..32w+32), one d/lane.
// ---------------------------------------------------------------------------
__global__ void __launch_bounds__(128) routing_kernel(const int* __restrict__ neighbors,
                                                      float* __restrict__ out)
{
    const int n     = blockIdx.x;
    const int tid   = threadIdx.x;
    const int w     = tid >> 5;
    const int lane  = tid & 31;
    const int c     = lane & 3;          // m-slot within reduce-scatter
    const int kk    = lane >> 2;         // this lane's capsule
    const bool b0   = (lane & 1) != 0;
    const bool b1   = (lane & 2) != 0;
    const int dmine = 32 * w + lane;     // this thread's d in reduce phase

    __shared__ float part[4 * 132];      // cross-warp partials (padded rows)
    __shared__ float u_s[D_DIM];         // u transpose buffer
    __shared__ float pex[4 * 96];        // per-warp p exchange: [k][q], stride 12

    // Warp w's 8 neighbor indices: lanes 0..7 load, distribute via shuffle.
    int r_my = 0;
    if (lane < 8) r_my = neighbors[(size_t)n * M_NB + w * 8 + lane];

    // Gather z rows as b64 pairs (zl = d[4l..4l+1], zh = d[4l+2..4l+3]).
    u64 zl[8], zh[8];
#pragma unroll
    for (int q = 0; q < 8; q++) {
        int r = __shfl_sync(FULLM, r_my, q);
        if ((unsigned)r < (unsigned)N_NODES) {
            uint4 t = __ldg(reinterpret_cast<const uint4*>(g_xn + (size_t)r * D_DIM + 4 * lane));
            ulonglong2 zz; memcpy(&zz, &t, 16);
            zl[q] = zz.x; zh[q] = zz.y;
        } else {
            zl[q] = 0ull; zh[q] = 0ull;  // padding row (index == N)
        }
    }

    const float xcs = __ldg(g_xn + (size_t)n * D_DIM + dmine);

    u64 ul, uh;   // u for this lane's d-slice, packed

    // ---- iteration 0: p = 1/8 uniformly ----
    {
        u64 a0 = 0ull, a1 = 0ull;
#pragma unroll
        for (int q = 0; q < 8; q++) { a0 = add2(a0, zl[q]); a1 = add2(a1, zh[q]); }
        const u64 eighth = pack2(0.125f, 0.125f);
        a0 = mul2(a0, eighth); a1 = mul2(a1, eighth);

        *reinterpret_cast<ulonglong2*>(&part[w * 132 + 4 * lane]) = make_ulonglong2(a0, a1);
        __syncthreads();

        float v = xcs;
#pragma unroll
        for (int w2 = 0; w2 < 4; w2++) v += part[w2 * 132 + dmine];

        float ss = v * v;                // capsule = 16 consecutive lanes
        ss += __shfl_xor_sync(FULLM, ss, 1);
        ss += __shfl_xor_sync(FULLM, ss, 2);
        ss += __shfl_xor_sync(FULLM, ss, 4);
        ss += __shfl_xor_sync(FULLM, ss, 8);
        float inv = rsqrtf(fmaxf(ss, EPS_N * EPS_N));
        u_s[dmine] = v * inv;
        __syncthreads();

        uint4 t = *reinterpret_cast<const uint4*>(&u_s[4 * lane]);
        ulonglong2 uu; memcpy(&uu, &t, 16);
        ul = uu.x; uh = uu.y;
    }

    // ---- iterations 1..5 ----
#pragma unroll
    for (int it = 1; it < MAX_IT; it++) {
        // lane-partial dots (f32x2): sp[q] = z[q][4l..4l+3] . u[4l..4l+3]
        float sp[8];
#pragma unroll
        for (int q = 0; q < 8; q++) {
            float2 f = unpack2(fma2(zl[q], ul, mul2(zh[q], uh)));
            sp[q] = f.x + f.y;
        }

        // reduce-scatter over xor1: a[j] = 2-lane sum of q = 2j + b0
        float a0, a1, a2, a3;
        {
            float sd, kp;
            sd = b0 ? sp[0] : sp[1]; kp = b0 ? sp[1] : sp[0];
            a0 = kp + __shfl_xor_sync(FULLM, sd, 1);
            sd = b0 ? sp[2] : sp[3]; kp = b0 ? sp[3] : sp[2];
            a1 = kp + __shfl_xor_sync(FULLM, sd, 1);
            sd = b0 ? sp[4] : sp[5]; kp = b0 ? sp[5] : sp[4];
            a2 = kp + __shfl_xor_sync(FULLM, sd, 1);
            sd = b0 ? sp[6] : sp[7]; kp = b0 ? sp[7] : sp[6];
            a3 = kp + __shfl_xor_sync(FULLM, sd, 1);
        }
        // reduce-scatter over xor2: s_i = full 16-dot for q = 4i + c
        float s0, s1;
        {
            float sd, kp;
            sd = b1 ? a0 : a1; kp = b1 ? a1 : a0;
            s0 = kp + __shfl_xor_sync(FULLM, sd, 2);
            sd = b1 ? a2 : a3; kp = b1 ? a3 : a2;
            s1 = kp + __shfl_xor_sync(FULLM, sd, 2);
        }

        // softmax over k. |s| <= 1 (unit x unit capsules) -> no max-sub.
        float e0 = __expf(s0), e1 = __expf(s1);
        float t0 = e0, t1 = e1;
        t0 += __shfl_xor_sync(FULLM, t0, 4);
        t1 += __shfl_xor_sync(FULLM, t1, 4);
        t0 += __shfl_xor_sync(FULLM, t0, 8);
        t1 += __shfl_xor_sync(FULLM, t1, 8);
        t0 += __shfl_xor_sync(FULLM, t0, 16);
        t1 += __shfl_xor_sync(FULLM, t1, 16);
        float p0 = __fdividef(e0, t0);   // p[q = c,     k = kk]
        float p1 = __fdividef(e1, t1);   // p[q = 4 + c, k = kk]

        // allgather p via smem: row kk holds p for q = 0..7 of this warp
        pex[w * 96 + kk * 12 + c]     = p0;
        pex[w * 96 + kk * 12 + 4 + c] = p1;
        __syncwarp();
        float pf[8];
        {
            float4 lo = *reinterpret_cast<const float4*>(&pex[w * 96 + kk * 12]);
            float4 hi = *reinterpret_cast<const float4*>(&pex[w * 96 + kk * 12 + 4]);
            pf[0] = lo.x; pf[1] = lo.y; pf[2] = lo.z; pf[3] = lo.w;
            pf[4] = hi.x; pf[5] = hi.y; pf[6] = hi.z; pf[7] = hi.w;
        }

        // weighted accumulation (f32x2)
        u64 acc0 = 0ull, acc1 = 0ull;
#pragma unroll
        for (int q = 0; q < 8; q++) {
            u64 pp = pack2(pf[q], pf[q]);
            acc0 = fma2(zl[q], pp, acc0);
            acc1 = fma2(zh[q], pp, acc1);
        }

        *reinterpret_cast<ulonglong2*>(&part[w * 132 + 4 * lane]) = make_ulonglong2(acc0, acc1);
        __syncthreads();

        // split-d reduce: this thread owns d = dmine
        float v = xcs;
#pragma unroll
        for (int w2 = 0; w2 < 4; w2++) v += part[w2 * 132 + dmine];

        if (it < MAX_IT - 1) {
            float ss = v * v;
            ss += __shfl_xor_sync(FULLM, ss, 1);
            ss += __shfl_xor_sync(FULLM, ss, 2);
            ss += __shfl_xor_sync(FULLM, ss, 4);
            ss += __shfl_xor_sync(FULLM, ss, 8);
            float inv = rsqrtf(fmaxf(ss, EPS_N * EPS_N));
            u_s[dmine] = v * inv;
            __syncthreads();
            uint4 t = *reinterpret_cast<const uint4*>(&u_s[4 * lane]);
            ulonglong2 uu; memcpy(&uu, &t, 16);
            ul = uu.x; uh = uu.y;
        } else {
            // last iteration: no renormalize; 128 threads write 512B coalesced
            out[(size_t)n * D_DIM + dmine] = v;
        }
    }
}

// ---------------------------------------------------------------------------
extern "C" void kernel_launch(void* const* d_in, const int* in_sizes, int n_in,
                              void* d_out, int out_size)
{
    const float* x   = (const float*)d_in[0];
    const int*   nb  = (const int*)d_in[1];
    float*       out = (float*)d_out;
    (void)in_sizes; (void)n_in; (void)out_size;

    int caps   = N_NODES * K_CAPS;
    int blocks = (caps + 63) / 64;
    caps_normalize_kernel<<<blocks, 256>>>(x);

    routing_kernel<<<N_NODES, 128>>>(nb, out);
}

// round 13
// speedup vs baseline: 1.6641x; 1.0175x over previous
#include <cuda_runtime.h>
#include <string.h>

// RoutingLayer: capsule dynamic routing.
//   N=50000, M=32 neighbors, D=128 = K(8) x 16, max_iter=6.
// Inputs: x fp32 [N,128], neighbors int32 [N*32], max_iter (fixed 6).
// Output: u fp32 [N,128].

#define N_NODES 50000
#define M_NB    32
#define D_DIM   128
#define K_CAPS  8
#define MAX_IT  6
#define EPS_N   1e-12f
#define FULLM   0xffffffffu

typedef unsigned long long u64;

// ---- f32x2 packed-math helpers (ptxas never auto-fuses FFMA2 from C++) ----
__device__ __forceinline__ u64 pack2(float a, float b) {
    u64 r; asm("mov.b64 %0,{%1,%2};" : "=l"(r) : "f"(a), "f"(b)); return r;
}
__device__ __forceinline__ float2 unpack2(u64 v) {
    float2 f; asm("mov.b64 {%0,%1},%2;" : "=f"(f.x), "=f"(f.y) : "l"(v)); return f;
}
__device__ __forceinline__ u64 fma2(u64 a, u64 b, u64 c) {
    u64 d; asm("fma.rn.f32x2 %0,%1,%2,%3;" : "=l"(d) : "l"(a), "l"(b), "l"(c)); return d;
}
__device__ __forceinline__ u64 mul2(u64 a, u64 b) {
    u64 d; asm("mul.rn.f32x2 %0,%1,%2;" : "=l"(d) : "l"(a), "l"(b)); return d;
}
__device__ __forceinline__ u64 add2(u64 a, u64 b) {
    u64 d; asm("add.rn.f32x2 %0,%1,%2;" : "=l"(d) : "l"(a), "l"(b)); return d;
}

// Scratch: per-capsule L2-normalized x.
__device__ float g_xn[(size_t)N_NODES * D_DIM];

// ---------------------------------------------------------------------------
// Kernel 1: per-capsule normalize x into g_xn (4 lanes per 16-wide capsule).
// ---------------------------------------------------------------------------
__global__ void __launch_bounds__(256) caps_normalize_kernel(const float* __restrict__ x)
{
    int c = blockIdx.x * 64 + (threadIdx.x >> 2);
    int j = threadIdx.x & 3;
    if (c >= N_NODES * K_CAPS) return;

    const float4 v = __ldg(reinterpret_cast<const float4*>(x + (size_t)c * 16 + 4 * j));
    float ss = v.x * v.x + v.y * v.y + v.z * v.z + v.w * v.w;
    ss += __shfl_xor_sync(FULLM, ss, 1);
    ss += __shfl_xor_sync(FULLM, ss, 2);
    float inv = 1.0f / fmaxf(sqrtf(ss), EPS_N);
    float4 o = make_float4(v.x * inv, v.y * inv, v.z * inv, v.w * inv);
    *reinterpret_cast<float4*>(g_xn + (size_t)c * 16 + 4 * j) = o;
}

// ---------------------------------------------------------------------------
// Kernel 2: routing. One 128-thread CTA per node, 9 CTAs/SM (regs <= 56).
//   p/acc-phase: warp w owns m {8w..8w+7}; lane owns d-slice [4l..4l+3]
//   (z as b64 pairs, math in f32x2). Dots via 6-shfl reduce-scatter;
//   softmax k-sums via 3-shfl butterflies (f32 REDUX not on sm_103);
//   p allgather via 384B/warp smem exchange (2 STS + 2 broadcast LDS.128).
//   reduce-phase (split-d): warp w reduces d in [32w..32w+32), one d/lane.
// ---------------------------------------------------------------------------
__global__ void __launch_bounds__(128, 9) routing_kernel(const int* __restrict__ neighbors,
                                                         float* __restrict__ out)
{
    const int n     = blockIdx.x;
    const int tid   = threadIdx.x;
    const int w     = tid >> 5;
    const int lane  = tid & 31;
    const int c     = lane & 3;          // m-slot within reduce-scatter
    const bool b0   = (lane & 1) != 0;
    const bool b1   = (lane & 2) != 0;
    const int dmine = 32 * w + lane;     // this thread's d in reduce phase

    __shared__ float part[4 * 132];      // cross-warp partials (padded rows)
    __shared__ float u_s[D_DIM];         // u transpose buffer
    __shared__ float pex[4 * 96];        // per-warp p exchange: [k][q], stride 12

    // hoisted pex row base for this thread: row = capsule kk = lane>>2
    float* const mypex = pex + w * 96 + (lane >> 2) * 12;

    // Warp w's 8 neighbor indices: lanes 0..7 load, distribute via shuffle.
    int r_my = 0;
    if (lane < 8) r_my = neighbors[(size_t)n * M_NB + w * 8 + lane];

    // Gather z rows as b64 pairs (zl = d[4l..4l+1], zh = d[4l+2..4l+3]).
    u64 zl[8], zh[8];
#pragma unroll
    for (int q = 0; q < 8; q++) {
        int r = __shfl_sync(FULLM, r_my, q);
        if ((unsigned)r < (unsigned)N_NODES) {
            uint4 t = __ldg(reinterpret_cast<const uint4*>(g_xn + (size_t)r * D_DIM + 4 * lane));
            ulonglong2 zz; memcpy(&zz, &t, 16);
            zl[q] = zz.x; zh[q] = zz.y;
        } else {
            zl[q] = 0ull; zh[q] = 0ull;  // padding row (index == N)
        }
    }

    const float xcs = __ldg(g_xn + (size_t)n * D_DIM + dmine);

    u64 ul, uh;   // u for this lane's d-slice, packed

    // ---- iteration 0: p = 1/8 uniformly ----
    {
        u64 a0 = 0ull, a1 = 0ull;
#pragma unroll
        for (int q = 0; q < 8; q++) { a0 = add2(a0, zl[q]); a1 = add2(a1, zh[q]); }
        const u64 eighth = pack2(0.125f, 0.125f);
        a0 = mul2(a0, eighth); a1 = mul2(a1, eighth);

        *reinterpret_cast<ulonglong2*>(&part[w * 132 + 4 * lane]) = make_ulonglong2(a0, a1);
        __syncthreads();

        float v = xcs;
#pragma unroll
        for (int w2 = 0; w2 < 4; w2++) v += part[w2 * 132 + dmine];

        float ss = v * v;                // capsule = 16 consecutive lanes
        ss += __shfl_xor_sync(FULLM, ss, 1);
        ss += __shfl_xor_sync(FULLM, ss, 2);
        ss += __shfl_xor_sync(FULLM, ss, 4);
        ss += __shfl_xor_sync(FULLM, ss, 8);
        float inv = rsqrtf(fmaxf(ss, EPS_N * EPS_N));
        u_s[dmine] = v * inv;
        __syncthreads();

        uint4 t = *reinterpret_cast<const uint4*>(&u_s[4 * lane]);
        ulonglong2 uu; memcpy(&uu, &t, 16);
        ul = uu.x; uh = uu.y;
    }

    // ---- iterations 1..5 ----
#pragma unroll
    for (int it = 1; it < MAX_IT; it++) {
        // lane-partial dots (f32x2): sp[q] = z[q][4l..4l+3] . u[4l..4l+3]
        float sp[8];
#pragma unroll
        for (int q = 0; q < 8; q++) {
            float2 f = unpack2(fma2(zl[q], ul, mul2(zh[q], uh)));
            sp[q] = f.x + f.y;
        }

        // reduce-scatter over xor1: a[j] = 2-lane sum of q = 2j + b0
        float a0, a1, a2, a3;
        {
            float sd, kp;
            sd = b0 ? sp[0] : sp[1]; kp = b0 ? sp[1] : sp[0];
            a0 = kp + __shfl_xor_sync(FULLM, sd, 1);
            sd = b0 ? sp[2] : sp[3]; kp = b0 ? sp[3] : sp[2];
            a1 = kp + __shfl_xor_sync(FULLM, sd, 1);
            sd = b0 ? sp[4] : sp[5]; kp = b0 ? sp[5] : sp[4];
            a2 = kp + __shfl_xor_sync(FULLM, sd, 1);
            sd = b0 ? sp[6] : sp[7]; kp = b0 ? sp[7] : sp[6];
            a3 = kp + __shfl_xor_sync(FULLM, sd, 1);
        }
        // reduce-scatter over xor2: s_i = full 16-dot for q = 4i + c
        float s0, s1;
        {
            float sd, kp;
            sd = b1 ? a0 : a1; kp = b1 ? a1 : a0;
            s0 = kp + __shfl_xor_sync(FULLM, sd, 2);
            sd = b1 ? a2 : a3; kp = b1 ? a3 : a2;
            s1 = kp + __shfl_xor_sync(FULLM, sd, 2);
        }

        // softmax over k. |s| <= 1 (unit x unit capsules) -> no max-sub.
        float e0 = __expf(s0), e1 = __expf(s1);
        float t0 = e0, t1 = e1;
        t0 += __shfl_xor_sync(FULLM, t0, 4);
        t1 += __shfl_xor_sync(FULLM, t1, 4);
        t0 += __shfl_xor_sync(FULLM, t0, 8);
        t1 += __shfl_xor_sync(FULLM, t1, 8);
        t0 += __shfl_xor_sync(FULLM, t0, 16);
        t1 += __shfl_xor_sync(FULLM, t1, 16);

        // allgather p via smem: row kk holds p for q = 0..7 of this warp
        mypex[c]     = __fdividef(e0, t0);   // p[q = c,     k = kk]
        mypex[4 + c] = __fdividef(e1, t1);   // p[q = 4 + c, k = kk]
        __syncwarp();
        const float4 lo = *reinterpret_cast<const float4*>(mypex);      // p[q=0..3]
        const float4 hi = *reinterpret_cast<const float4*>(mypex + 4);  // p[q=4..7]

        // weighted accumulation (f32x2), consuming lo/hi directly
        u64 acc0 = 0ull, acc1 = 0ull;
        {
            u64 pp;
            pp = pack2(lo.x, lo.x); acc0 = fma2(zl[0], pp, acc0); acc1 = fma2(zh[0], pp, acc1);
            pp = pack2(lo.y, lo.y); acc0 = fma2(zl[1], pp, acc0); acc1 = fma2(zh[1], pp, acc1);
            pp = pack2(lo.z, lo.z); acc0 = fma2(zl[2], pp, acc0); acc1 = fma2(zh[2], pp, acc1);
            pp = pack2(lo.w, lo.w); acc0 = fma2(zl[3], pp, acc0); acc1 = fma2(zh[3], pp, acc1);
            pp = pack2(hi.x, hi.x); acc0 = fma2(zl[4], pp, acc0); acc1 = fma2(zh[4], pp, acc1);
            pp = pack2(hi.y, hi.y); acc0 = fma2(zl[5], pp, acc0); acc1 = fma2(zh[5], pp, acc1);
            pp = pack2(hi.z, hi.z); acc0 = fma2(zl[6], pp, acc0); acc1 = fma2(zh[6], pp, acc1);
            pp = pack2(hi.w, hi.w); acc0 = fma2(zl[7], pp, acc0); acc1 = fma2(zh[7], pp, acc1);
        }

        *reinterpret_cast<ulonglong2*>(&part[w * 132 + 4 * lane]) = make_ulonglong2(acc0, acc1);
        __syncthreads();

        // split-d reduce: this thread owns d = dmine
        float v = xcs;
#pragma unroll
        for (int w2 = 0; w2 < 4; w2++) v += part[w2 * 132 + dmine];

        if (it < MAX_IT - 1) {
            float ss = v * v;
            ss += __shfl_xor_sync(FULLM, ss, 1);
            ss += __shfl_xor_sync(FULLM, ss, 2);
            ss += __shfl_xor_sync(FULLM, ss, 4);
            ss += __shfl_xor_sync(FULLM, ss, 8);
            float inv = rsqrtf(fmaxf(ss, EPS_N * EPS_N));
            u_s[dmine] = v * inv;
            __syncthreads();
            uint4 t = *reinterpret_cast<const uint4*>(&u_s[4 * lane]);
            ulonglong2 uu; memcpy(&uu, &t, 16);
            ul = uu.x; uh = uu.y;
        } else {
            // last iteration: no renormalize; 128 threads write 512B coalesced
            out[(size_t)n * D_DIM + dmine] = v;
        }
    }
}

// ---------------------------------------------------------------------------
extern "C" void kernel_launch(void* const* d_in, const int* in_sizes, int n_in,
                              void* d_out, int out_size)
{
    const float* x   = (const float*)d_in[0];
    const int*   nb  = (const int*)d_in[1];
    float*       out = (float*)d_out;
    (void)in_sizes; (void)n_in; (void)out_size;

    int caps   = N_NODES * K_CAPS;
    int blocks = (caps + 63) / 64;
    caps_normalize_kernel<<<blocks, 256>>>(x);

    routing_kernel<<<N_NODES, 128>>>(nb, out);
}

// round 14
// speedup vs baseline: 1.7195x; 1.0333x over previous
#include <cuda_runtime.h>
#include <string.h>

// RoutingLayer: capsule dynamic routing.
//   N=50000, M=32 neighbors, D=128 = K(8) x 16, max_iter=6.
// Inputs: x fp32 [N,128], neighbors int32 [N*32], max_iter (fixed 6).
// Output: u fp32 [N,128].

#define N_NODES 50000
#define M_NB    32
#define D_DIM   128
#define K_CAPS  8
#define MAX_IT  6
#define EPS_N   1e-12f
#define FULLM   0xffffffffu

typedef unsigned long long u64;

// ---- f32x2 packed-math helpers (ptxas never auto-fuses FFMA2 from C++) ----
__device__ __forceinline__ u64 pack2(float a, float b) {
    u64 r; asm("mov.b64 %0,{%1,%2};" : "=l"(r) : "f"(a), "f"(b)); return r;
}
__device__ __forceinline__ float2 unpack2(u64 v) {
    float2 f; asm("mov.b64 {%0,%1},%2;" : "=f"(f.x), "=f"(f.y) : "l"(v)); return f;
}
__device__ __forceinline__ u64 fma2(u64 a, u64 b, u64 c) {
    u64 d; asm("fma.rn.f32x2 %0,%1,%2,%3;" : "=l"(d) : "l"(a), "l"(b), "l"(c)); return d;
}
__device__ __forceinline__ u64 mul2(u64 a, u64 b) {
    u64 d; asm("mul.rn.f32x2 %0,%1,%2;" : "=l"(d) : "l"(a), "l"(b)); return d;
}
__device__ __forceinline__ u64 add2(u64 a, u64 b) {
    u64 d; asm("add.rn.f32x2 %0,%1,%2;" : "=l"(d) : "l"(a), "l"(b)); return d;
}

// Scratch: per-capsule L2-normalized x.
__device__ float g_xn[(size_t)N_NODES * D_DIM];

// ---------------------------------------------------------------------------
// Kernel 1: per-capsule normalize x into g_xn (4 lanes per 16-wide capsule).
// ---------------------------------------------------------------------------
__global__ void __launch_bounds__(256) caps_normalize_kernel(const float* __restrict__ x)
{
    int c = blockIdx.x * 64 + (threadIdx.x >> 2);
    int j = threadIdx.x & 3;
    if (c >= N_NODES * K_CAPS) return;

    const float4 v = __ldg(reinterpret_cast<const float4*>(x + (size_t)c * 16 + 4 * j));
    float ss = v.x * v.x + v.y * v.y + v.z * v.z + v.w * v.w;
    ss += __shfl_xor_sync(FULLM, ss, 1);
    ss += __shfl_xor_sync(FULLM, ss, 2);
    float inv = 1.0f / fmaxf(sqrtf(ss), EPS_N);
    float4 o = make_float4(v.x * inv, v.y * inv, v.z * inv, v.w * inv);
    *reinterpret_cast<float4*>(g_xn + (size_t)c * 16 + 4 * j) = o;
}

// ---------------------------------------------------------------------------
// Kernel 2: routing. One 128-thread CTA per node, 9 CTAs/SM (regs <= 56).
//   warp w owns m {8w..8w+7}; lane owns d-slice [4l..4l+3] (z as b64 pairs).
//   Renormalize is FOLDED into the dot: u_s carries raw v; the p-phase
//   computes inv_k = rsqrt(||v||^2) via a lane-local v.v partial + 2-shfl
//   allreduce and scales the raw dots. Softmax denominators via a 2-value
//   reduce-scatter (4 shfl instead of 6 butterflies). p allgather via
//   384B/warp smem exchange. Split-d reduce: warp w owns d in [32w,32w+32).
// ---------------------------------------------------------------------------
__global__ void __launch_bounds__(128, 9) routing_kernel(const int* __restrict__ neighbors,
                                                         float* __restrict__ out)
{
    const int n     = blockIdx.x;
    const int tid   = threadIdx.x;
    const int w     = tid >> 5;
    const int lane  = tid & 31;
    const int c     = lane & 3;          // m-slot within reduce-scatter
    const bool b0   = (lane & 1) != 0;
    const bool b1   = (lane & 2) != 0;
    const bool b2   = (lane & 4) != 0;
    const int dmine = 32 * w + lane;     // this thread's d in reduce phase

    __shared__ float part[4 * 132];      // cross-warp partials (padded rows)
    __shared__ float u_s[D_DIM];         // raw v transpose buffer
    __shared__ float pex[4 * 96];        // per-warp p exchange: [k][q], stride 12

    // hoisted pex row base for this thread: row = capsule kk = lane>>2
    float* const mypex = pex + w * 96 + (lane >> 2) * 12;

    // Warp w's 8 neighbor indices: lanes 0..7 load, distribute via shuffle.
    int r_my = 0;
    if (lane < 8) r_my = neighbors[(size_t)n * M_NB + w * 8 + lane];

    // Gather z rows as b64 pairs (zl = d[4l..4l+1], zh = d[4l+2..4l+3]).
    u64 zl[8], zh[8];
#pragma unroll
    for (int q = 0; q < 8; q++) {
        int r = __shfl_sync(FULLM, r_my, q);
        if ((unsigned)r < (unsigned)N_NODES) {
            uint4 t = __ldg(reinterpret_cast<const uint4*>(g_xn + (size_t)r * D_DIM + 4 * lane));
            ulonglong2 zz; memcpy(&zz, &t, 16);
            zl[q] = zz.x; zh[q] = zz.y;
        } else {
            zl[q] = 0ull; zh[q] = 0ull;  // padding row (index == N)
        }
    }

    const float xcs = __ldg(g_xn + (size_t)n * D_DIM + dmine);

    u64 ul, uh;   // RAW v for this lane's d-slice, packed

    // ---- iteration 0: p = 1/8 uniformly; store raw v (no renorm) ----
    {
        u64 a0 = 0ull, a1 = 0ull;
#pragma unroll
        for (int q = 0; q < 8; q++) { a0 = add2(a0, zl[q]); a1 = add2(a1, zh[q]); }
        const u64 eighth = pack2(0.125f, 0.125f);
        a0 = mul2(a0, eighth); a1 = mul2(a1, eighth);

        *reinterpret_cast<ulonglong2*>(&part[w * 132 + 4 * lane]) = make_ulonglong2(a0, a1);
        __syncthreads();

        float v = xcs;
#pragma unroll
        for (int w2 = 0; w2 < 4; w2++) v += part[w2 * 132 + dmine];
        u_s[dmine] = v;                  // raw, unnormalized
        __syncthreads();

        uint4 t = *reinterpret_cast<const uint4*>(&u_s[4 * lane]);
        ulonglong2 uu; memcpy(&uu, &t, 16);
        ul = uu.x; uh = uu.y;
    }

    // ---- iterations 1..5 ----
#pragma unroll
    for (int it = 1; it < MAX_IT; it++) {
        // per-capsule ||v||^2: lane partial + 2-shfl allreduce over 4-lane group
        float inv;
        {
            float2 f = unpack2(fma2(ul, ul, mul2(uh, uh)));
            float ssq = f.x + f.y;
            ssq += __shfl_xor_sync(FULLM, ssq, 1);
            ssq += __shfl_xor_sync(FULLM, ssq, 2);
            inv = rsqrtf(fmaxf(ssq, EPS_N * EPS_N));   // 1/max(||v||, eps)
        }

        // lane-partial raw dots (f32x2): sp[q] = z[q][4l..4l+3] . v[4l..4l+3]
        float sp[8];
#pragma unroll
        for (int q = 0; q < 8; q++) {
            float2 f = unpack2(fma2(zl[q], ul, mul2(zh[q], uh)));
            sp[q] = f.x + f.y;
        }

        // reduce-scatter over xor1: a[j] = 2-lane sum of q = 2j + b0
        float a0, a1, a2, a3;
        {
            float sd, kp;
            sd = b0 ? sp[0] : sp[1]; kp = b0 ? sp[1] : sp[0];
            a0 = kp + __shfl_xor_sync(FULLM, sd, 1);
            sd = b0 ? sp[2] : sp[3]; kp = b0 ? sp[3] : sp[2];
            a1 = kp + __shfl_xor_sync(FULLM, sd, 1);
            sd = b0 ? sp[4] : sp[5]; kp = b0 ? sp[5] : sp[4];
            a2 = kp + __shfl_xor_sync(FULLM, sd, 1);
            sd = b0 ? sp[6] : sp[7]; kp = b0 ? sp[7] : sp[6];
            a3 = kp + __shfl_xor_sync(FULLM, sd, 1);
        }
        // reduce-scatter over xor2: s_i = full 16-dot for q = 4i + c
        float s0, s1;
        {
            float sd, kp;
            sd = b1 ? a0 : a1; kp = b1 ? a1 : a0;
            s0 = kp + __shfl_xor_sync(FULLM, sd, 2);
            sd = b1 ? a2 : a3; kp = b1 ? a3 : a2;
            s1 = kp + __shfl_xor_sync(FULLM, sd, 2);
        }

        // fold the renormalize: s = (z.v) * inv_k.  |s| <= 1 -> no max-sub.
        float e0 = __expf(s0 * inv);
        float e1 = __expf(s1 * inv);

        // softmax denominators over k (8 lanes, stride 4) via 2-value RS:
        // stage xor4 scatters (t0|t1), xor8/xor16 allreduce, xor4 exchange.
        float t0, t1;
        {
            float sd = b2 ? e0 : e1;
            float kp = b2 ? e1 : e0;
            float g  = kp + __shfl_xor_sync(FULLM, sd, 4);  // partial t_{b2}
            g += __shfl_xor_sync(FULLM, g, 8);
            g += __shfl_xor_sync(FULLM, g, 16);             // full t_{b2}
            float h = __shfl_xor_sync(FULLM, g, 4);         // partner's t
            t0 = b2 ? h : g;
            t1 = b2 ? g : h;
        }

        // allgather p via smem: row kk holds p for q = 0..7 of this warp
        mypex[c]     = __fdividef(e0, t0);   // p[q = c,     k = kk]
        mypex[4 + c] = __fdividef(e1, t1);   // p[q = 4 + c, k = kk]
        __syncwarp();
        const float4 lo = *reinterpret_cast<const float4*>(mypex);      // p[q=0..3]
        const float4 hi = *reinterpret_cast<const float4*>(mypex + 4);  // p[q=4..7]

        // weighted accumulation (f32x2), consuming lo/hi directly
        u64 acc0 = 0ull, acc1 = 0ull;
        {
            u64 pp;
            pp = pack2(lo.x, lo.x); acc0 = fma2(zl[0], pp, acc0); acc1 = fma2(zh[0], pp, acc1);
            pp = pack2(lo.y, lo.y); acc0 = fma2(zl[1], pp, acc0); acc1 = fma2(zh[1], pp, acc1);
            pp = pack2(lo.z, lo.z); acc0 = fma2(zl[2], pp, acc0); acc1 = fma2(zh[2], pp, acc1);
            pp = pack2(lo.w, lo.w); acc0 = fma2(zl[3], pp, acc0); acc1 = fma2(zh[3], pp, acc1);
            pp = pack2(hi.x, hi.x); acc0 = fma2(zl[4], pp, acc0); acc1 = fma2(zh[4], pp, acc1);
            pp = pack2(hi.y, hi.y); acc0 = fma2(zl[5], pp, acc0); acc1 = fma2(zh[5], pp, acc1);
            pp = pack2(hi.z, hi.z); acc0 = fma2(zl[6], pp, acc0); acc1 = fma2(zh[6], pp, acc1);
            pp = pack2(hi.w, hi.w); acc0 = fma2(zl[7], pp, acc0); acc1 = fma2(zh[7], pp, acc1);
        }

        *reinterpret_cast<ulonglong2*>(&part[w * 132 + 4 * lane]) = make_ulonglong2(acc0, acc1);
        __syncthreads();

        // split-d reduce: this thread owns d = dmine (no renorm here anymore)
        float v = xcs;
#pragma unroll
        for (int w2 = 0; w2 < 4; w2++) v += part[w2 * 132 + dmine];

        if (it < MAX_IT - 1) {
            u_s[dmine] = v;              // raw v; normalization folded into dots
            __syncthreads();
            uint4 t = *reinterpret_cast<const uint4*>(&u_s[4 * lane]);
            ulonglong2 uu; memcpy(&uu, &t, 16);
            ul = uu.x; uh = uu.y;
        } else {
            // last iteration: reference leaves u unnormalized; write result
            out[(size_t)n * D_DIM + dmine] = v;
        }
    }
}

// ---------------------------------------------------------------------------
extern "C" void kernel_launch(void* const* d_in, const int* in_sizes, int n_in,
                              void* d_out, int out_size)
{
    const float* x   = (const float*)d_in[0];
    const int*   nb  = (const int*)d_in[1];
    float*       out = (float*)d_out;
    (void)in_sizes; (void)n_in; (void)out_size;

    int caps   = N_NODES * K_CAPS;
    int blocks = (caps + 63) / 64;
    caps_normalize_kernel<<<blocks, 256>>>(x);

    routing_kernel<<<N_NODES, 128>>>(nb, out);
}